// round 5
// baseline (speedup 1.0000x reference)
#include <cuda_runtime.h>
#include <cstdint>

#define TOKENS 32768          // 8 * 4096
#define INDIM  512
#define CBK    8192
#define CBD    16
#define CCHUNK 512            // codes staged to smem per iteration

// ---------------- scratch (device globals; no allocation allowed) ----------------
__device__ __align__(16) float g_targets[TOKENS * CBD];  // 2 MB
__device__ __align__(16) float g_c2[CBK];                // 32 KB

// ---------------- kernel 1: codebook squared norms ----------------
__global__ void kc2(const float* __restrict__ cb) {
    int k = blockIdx.x * 256 + threadIdx.x;
    if (k >= CBK) return;
    const float* row = cb + (size_t)k * CBD;
    float s = 0.f;
#pragma unroll
    for (int i = 0; i < CBD; ++i) s = fmaf(row[i], row[i], s);
    g_c2[k] = s;
}

// ---------------- kernel 2: projection  t[r][j] = sum_d x[r][d] * W[j][d] ----------------
__global__ void __launch_bounds__(128) kproj(const float* __restrict__ in,
                                             const float* __restrict__ W) {
    __shared__ __align__(16) float sW[CBD * INDIM];   // W as-is, row j contiguous (32 KB)
    int tid = threadIdx.x;
    for (int i = tid; i < CBD * INDIM / 4; i += 128)
        reinterpret_cast<float4*>(sW)[i] = reinterpret_cast<const float4*>(W)[i];
    __syncthreads();

    int r = blockIdx.x * 128 + tid;                   // 256 blocks -> all 32768 rows
    const float4* x4 = reinterpret_cast<const float4*>(in + (size_t)r * INDIM);

    float acc[CBD];
#pragma unroll
    for (int j = 0; j < CBD; ++j) acc[j] = 0.f;

    for (int d4 = 0; d4 < INDIM / 4; ++d4) {
        float4 xv = x4[d4];
#pragma unroll
        for (int j = 0; j < CBD; ++j) {
            float4 wv = reinterpret_cast<const float4*>(sW + j * INDIM)[d4];  // warp-broadcast
            acc[j] = fmaf(xv.x, wv.x, acc[j]);
            acc[j] = fmaf(xv.y, wv.y, acc[j]);
            acc[j] = fmaf(xv.z, wv.z, acc[j]);
            acc[j] = fmaf(xv.w, wv.w, acc[j]);
        }
    }

    float4* o4 = reinterpret_cast<float4*>(g_targets + (size_t)r * CBD);
#pragma unroll
    for (int q = 0; q < 4; ++q) {
        float4 o;
        o.x = acc[4 * q + 0]; o.y = acc[4 * q + 1];
        o.z = acc[4 * q + 2]; o.w = acc[4 * q + 3];
        o4[q] = o;
    }
}

// ---------------- kernel 3: full argmin scan, one thread = one token ----------------
__global__ void __launch_bounds__(128) kdist(const float* __restrict__ cb,
                                             float* __restrict__ out) {
    __shared__ __align__(16) float sC[CCHUNK * CBD];  // 32 KB codebook chunk
    __shared__ float sN[CCHUNK];                      // 2 KB norms

    int tid   = threadIdx.x;
    int token = blockIdx.x * 128 + tid;

    // target registers + ||t||^2
    float t[CBD];
    {
        const float4* t4 = reinterpret_cast<const float4*>(g_targets + (size_t)token * CBD);
        float4 a = t4[0], b = t4[1], c = t4[2], d = t4[3];
        t[0]=a.x;  t[1]=a.y;  t[2]=a.z;  t[3]=a.w;
        t[4]=b.x;  t[5]=b.y;  t[6]=b.z;  t[7]=b.w;
        t[8]=c.x;  t[9]=c.y;  t[10]=c.z; t[11]=c.w;
        t[12]=d.x; t[13]=d.y; t[14]=d.z; t[15]=d.w;
    }
    float t2 = 0.f;
#pragma unroll
    for (int i = 0; i < CBD; ++i) t2 = fmaf(t[i], t[i], t2);

    float best = __int_as_float(0x7F800000);   // +inf
    int   bid  = 0;

    for (int c0 = 0; c0 < CBK; c0 += CCHUNK) {
        __syncthreads();   // previous chunk's readers are done
        // stage chunk: 512 codes x 16 floats, contiguous
        const float4* src = reinterpret_cast<const float4*>(cb + (size_t)c0 * CBD);
        for (int i = tid; i < CCHUNK * CBD / 4; i += 128)
            reinterpret_cast<float4*>(sC)[i] = src[i];
        for (int i = tid; i < CCHUNK; i += 128)
            sN[i] = g_c2[c0 + i];
        __syncthreads();

#pragma unroll 2
        for (int k = 0; k < CCHUNK; k += 2) {
            const float4* cp0 = reinterpret_cast<const float4*>(sC + (k)     * CBD);
            const float4* cp1 = reinterpret_cast<const float4*>(sC + (k + 1) * CBD);
            float4 a0 = cp0[0], b0 = cp0[1], c0v = cp0[2], d0v = cp0[3];
            float4 a1 = cp1[0], b1 = cp1[1], c1v = cp1[2], d1v = cp1[3];

            float s0 = t[0] * a0.x;             float s1 = t[0] * a1.x;
            s0 = fmaf(t[1],  a0.y, s0);         s1 = fmaf(t[1],  a1.y, s1);
            s0 = fmaf(t[2],  a0.z, s0);         s1 = fmaf(t[2],  a1.z, s1);
            s0 = fmaf(t[3],  a0.w, s0);         s1 = fmaf(t[3],  a1.w, s1);
            s0 = fmaf(t[4],  b0.x, s0);         s1 = fmaf(t[4],  b1.x, s1);
            s0 = fmaf(t[5],  b0.y, s0);         s1 = fmaf(t[5],  b1.y, s1);
            s0 = fmaf(t[6],  b0.z, s0);         s1 = fmaf(t[6],  b1.z, s1);
            s0 = fmaf(t[7],  b0.w, s0);         s1 = fmaf(t[7],  b1.w, s1);
            s0 = fmaf(t[8],  c0v.x, s0);        s1 = fmaf(t[8],  c1v.x, s1);
            s0 = fmaf(t[9],  c0v.y, s0);        s1 = fmaf(t[9],  c1v.y, s1);
            s0 = fmaf(t[10], c0v.z, s0);        s1 = fmaf(t[10], c1v.z, s1);
            s0 = fmaf(t[11], c0v.w, s0);        s1 = fmaf(t[11], c1v.w, s1);
            s0 = fmaf(t[12], d0v.x, s0);        s1 = fmaf(t[12], d1v.x, s1);
            s0 = fmaf(t[13], d0v.y, s0);        s1 = fmaf(t[13], d1v.y, s1);
            s0 = fmaf(t[14], d0v.z, s0);        s1 = fmaf(t[14], d1v.z, s1);
            s0 = fmaf(t[15], d0v.w, s0);        s1 = fmaf(t[15], d1v.w, s1);

            // mirror reference rounding: (t2 - 2*cross) + c2, unfused
            float dA = __fadd_rn(__fsub_rn(t2, __fmul_rn(2.f, s0)), sN[k]);
            float dB = __fadd_rn(__fsub_rn(t2, __fmul_rn(2.f, s1)), sN[k + 1]);
            if (dA < best) { best = dA; bid = c0 + k; }
            if (dB < best) { best = dB; bid = c0 + k + 1; }
        }
    }

    // __output__ dtype is float32: labels <= 8191 are exactly representable
    out[token] = (float)bid;
}

// ---------------- launch ----------------
extern "C" void kernel_launch(void* const* d_in, const int* in_sizes, int n_in,
                              void* d_out, int out_size) {
    // Dispatch by element count (all three are pairwise distinct):
    //   input_values 16777216, proj_weight 8192, code_book 131072
    const float* in = nullptr;
    const float* W  = nullptr;
    const float* cb = nullptr;
    for (int i = 0; i < n_in; ++i) {
        if      (in_sizes[i] == TOKENS * INDIM) in = (const float*)d_in[i];
        else if (in_sizes[i] == CBD * INDIM)    W  = (const float*)d_in[i];
        else if (in_sizes[i] == CBK * CBD)      cb = (const float*)d_in[i];
    }
    if (!in) in = (const float*)d_in[0];   // positional fallback
    if (!W)  W  = (const float*)d_in[1];
    if (!cb) cb = (const float*)d_in[2];
    float* out = (float*)d_out;

    kc2  <<<CBK / 256, 256>>>(cb);
    kproj<<<TOKENS / 128, 128>>>(in, W);
    kdist<<<TOKENS / 128, 128>>>(cb, out);
}

// round 6
// speedup vs baseline: 1.4922x; 1.4922x over previous
#include <cuda_runtime.h>
#include <cstdint>

typedef unsigned long long ull;

#define TOKENS 32768
#define INDIM  512
#define CBK    8192
#define CBD    16
#define NPAIR  4096          // 8192 codes as 4096 pairs
#define SPLITS 4
#define PAIRS_PER_SPLIT (NPAIR / SPLITS)   // 1024
#define CHUNK  128           // pairs staged per chunk
#define NCHUNKS (PAIRS_PER_SPLIT / CHUNK)  // 8

// ---------------- scratch (device globals; no allocation allowed) ----------------
__device__ __align__(16) float g_targets[TOKENS * CBD];      // 2 MB
__device__ __align__(16) float g_cbpairs[NPAIR * 32];        // interleaved (cA_i, cB_i), 512 KB
__device__ __align__(16) float g_c2[NPAIR * 2];              // (||cA||^2, ||cB||^2), 32 KB
__device__ ull g_packed[TOKENS];                             // sortable-key<<32 | idx

// ---------------- f32x2 helpers (packed fp32, sm_100+) ----------------
__device__ __forceinline__ ull ffma2(ull a, ull b, ull c) {
    ull d; asm("fma.rn.f32x2 %0, %1, %2, %3;" : "=l"(d) : "l"(a), "l"(b), "l"(c)); return d;
}
__device__ __forceinline__ ull mul2(ull a, ull b) {
    ull d; asm("mul.rn.f32x2 %0, %1, %2;" : "=l"(d) : "l"(a), "l"(b)); return d;
}
__device__ __forceinline__ ull add2(ull a, ull b) {
    ull d; asm("add.rn.f32x2 %0, %1, %2;" : "=l"(d) : "l"(a), "l"(b)); return d;
}
__device__ __forceinline__ ull pack2(float lo, float hi) {
    ull d; asm("mov.b64 %0, {%1, %2};" : "=l"(d) : "f"(lo), "f"(hi)); return d;
}
__device__ __forceinline__ void unpack2(ull v, float& lo, float& hi) {
    asm("mov.b64 {%0, %1}, %2;" : "=f"(lo), "=f"(hi) : "l"(v));
}
__device__ __forceinline__ void cp16(uint32_t saddr, const void* g) {
    asm volatile("cp.async.cg.shared.global [%0], [%1], 16;" :: "r"(saddr), "l"(g));
}

// ---------------- kernel 0a: init packed mins ----------------
__global__ void kinit() {
    int i = blockIdx.x * blockDim.x + threadIdx.x;
    if (i < TOKENS) g_packed[i] = ~0ull;
}

// ---------------- kernel 0b: interleaved codebook + norms ----------------
__global__ void kprep(const float* __restrict__ cb) {
    int p = blockIdx.x * blockDim.x + threadIdx.x;
    if (p >= NPAIR) return;
    const float* a = cb + (size_t)(2 * p) * CBD;
    const float* b = a + CBD;
    float c2a = 0.f, c2b = 0.f;
#pragma unroll
    for (int i = 0; i < CBD; ++i) {
        float av = a[i], bv = b[i];
        g_cbpairs[p * 32 + 2 * i]     = av;
        g_cbpairs[p * 32 + 2 * i + 1] = bv;
        c2a = fmaf(av, av, c2a);
        c2b = fmaf(bv, bv, c2b);
    }
    g_c2[2 * p]     = c2a;
    g_c2[2 * p + 1] = c2b;
}

// ---------------- kernel 1: projection  t[r][j] = sum_d x[r][d] * W[j][d] ----------------
__global__ void __launch_bounds__(128) k1(const float* __restrict__ in, const float* __restrict__ W) {
    __shared__ __align__(16) float sWt[INDIM * CBD];   // transposed W: [d][j], 32 KB
    int tid = threadIdx.x;
    for (int idx = tid; idx < CBD * INDIM; idx += 128) {
        int j = idx >> 9;          // 0..15
        int d = idx & 511;
        sWt[d * CBD + j] = W[idx];
    }
    __syncthreads();

    int r = blockIdx.x * 128 + tid;
    const float4* xin = reinterpret_cast<const float4*>(in + (size_t)r * INDIM);
    ull acc[8];
#pragma unroll
    for (int k = 0; k < 8; ++k) acc[k] = 0ull;

#pragma unroll 2
    for (int d4 = 0; d4 < INDIM / 4; ++d4) {
        float4 xv = xin[d4];
        float xs[4] = {xv.x, xv.y, xv.z, xv.w};
#pragma unroll
        for (int dd = 0; dd < 4; ++dd) {
            ull xd = pack2(xs[dd], xs[dd]);
            const ulonglong2* wd = reinterpret_cast<const ulonglong2*>(sWt + (d4 * 4 + dd) * CBD);
            ulonglong2 w0 = wd[0], w1 = wd[1], w2 = wd[2], w3 = wd[3];
            acc[0] = ffma2(w0.x, xd, acc[0]); acc[1] = ffma2(w0.y, xd, acc[1]);
            acc[2] = ffma2(w1.x, xd, acc[2]); acc[3] = ffma2(w1.y, xd, acc[3]);
            acc[4] = ffma2(w2.x, xd, acc[4]); acc[5] = ffma2(w2.y, xd, acc[5]);
            acc[6] = ffma2(w3.x, xd, acc[6]); acc[7] = ffma2(w3.y, xd, acc[7]);
        }
    }

    float4* out4 = reinterpret_cast<float4*>(g_targets + (size_t)r * CBD);
    float4 o;
    unpack2(acc[0], o.x, o.y); unpack2(acc[1], o.z, o.w); out4[0] = o;
    unpack2(acc[2], o.x, o.y); unpack2(acc[3], o.z, o.w); out4[1] = o;
    unpack2(acc[4], o.x, o.y); unpack2(acc[5], o.z, o.w); out4[2] = o;
    unpack2(acc[6], o.x, o.y); unpack2(acc[7], o.z, o.w); out4[3] = o;
}

// ---------------- kernel 2: argmin(||c||^2 - 2 t.c), 4-way codebook split ----------------
__global__ void __launch_bounds__(128, 3) k2() {
    __shared__ __align__(16) float sD[2][CHUNK * 32];   // 16 KB per buffer
    __shared__ __align__(16) float sC2[2][CHUNK * 2];   // 1 KB per buffer

    int tid   = threadIdx.x;
    int split = blockIdx.x & (SPLITS - 1);
    int token = (blockIdx.x >> 2) * 128 + tid;
    int baseP = split * PAIRS_PER_SPLIT;

    const float4* t4 = reinterpret_cast<const float4*>(g_targets + (size_t)token * CBD);
    float tt[16];
    {
        float4 a = t4[0], b = t4[1], c = t4[2], d = t4[3];
        tt[0]=a.x;  tt[1]=a.y;  tt[2]=a.z;  tt[3]=a.w;
        tt[4]=b.x;  tt[5]=b.y;  tt[6]=b.z;  tt[7]=b.w;
        tt[8]=c.x;  tt[9]=c.y;  tt[10]=c.z; tt[11]=c.w;
        tt[12]=d.x; tt[13]=d.y; tt[14]=d.z; tt[15]=d.w;
    }
    ull td[16];
#pragma unroll
    for (int i = 0; i < 16; ++i) td[i] = pack2(tt[i], tt[i]);

    const ull NEG2 = pack2(-2.f, -2.f);
    float minv = __int_as_float(0x7F800000);   // +inf
    int   mini = 0;

    auto stage = [&](int chunk, int buf) {
        const float4* src = reinterpret_cast<const float4*>(g_cbpairs + (size_t)(baseP + chunk * CHUNK) * 32);
        uint32_t sd = (uint32_t)__cvta_generic_to_shared(&sD[buf][0]);
        for (int k = tid; k < CHUNK * 8; k += 128)            // 1024 x 16B
            cp16(sd + k * 16, src + k);
        const float4* s2 = reinterpret_cast<const float4*>(g_c2 + (size_t)(baseP + chunk * CHUNK) * 2);
        uint32_t sc = (uint32_t)__cvta_generic_to_shared(&sC2[buf][0]);
        if (tid < CHUNK * 2 / 4)                               // 64 x 16B
            cp16(sc + tid * 16, s2 + tid);
        asm volatile("cp.async.commit_group;" ::: "memory");
    };

    int buf = 0;
    stage(0, 0);
    for (int chunk = 0; chunk < NCHUNKS; ++chunk) {
        if (chunk + 1 < NCHUNKS) {
            stage(chunk + 1, buf ^ 1);
            asm volatile("cp.async.wait_group 1;" ::: "memory");
        } else {
            asm volatile("cp.async.wait_group 0;" ::: "memory");
        }
        __syncthreads();

        const float* sdp = sD[buf];
        const ull*   c2p = reinterpret_cast<const ull*>(&sC2[buf][0]);
        int gp0 = baseP + chunk * CHUNK;

#pragma unroll 2
        for (int p = 0; p < CHUNK; ++p) {
            const ulonglong2* cp = reinterpret_cast<const ulonglong2*>(sdp + p * 32);
            ulonglong2 q0 = cp[0], q1 = cp[1], q2 = cp[2], q3 = cp[3];
            ulonglong2 q4 = cp[4], q5 = cp[5], q6 = cp[6], q7 = cp[7];
            ull s0 = mul2 (q0.x, td[0]);        ull s1 = mul2 (q0.y, td[1]);
            s0 = ffma2(q1.x, td[2],  s0);       s1 = ffma2(q1.y, td[3],  s1);
            s0 = ffma2(q2.x, td[4],  s0);       s1 = ffma2(q2.y, td[5],  s1);
            s0 = ffma2(q3.x, td[6],  s0);       s1 = ffma2(q3.y, td[7],  s1);
            s0 = ffma2(q4.x, td[8],  s0);       s1 = ffma2(q4.y, td[9],  s1);
            s0 = ffma2(q5.x, td[10], s0);       s1 = ffma2(q5.y, td[11], s1);
            s0 = ffma2(q6.x, td[12], s0);       s1 = ffma2(q6.y, td[13], s1);
            s0 = ffma2(q7.x, td[14], s0);       s1 = ffma2(q7.y, td[15], s1);
            ull s  = add2(s0, s1);
            ull sc = ffma2(s, NEG2, c2p[p]);    // score = ||c||^2 - 2 t.c  (per half)
            float lo, hi; unpack2(sc, lo, hi);
            int ib = 2 * (gp0 + p);
            if (lo < minv) { minv = lo; mini = ib; }
            if (hi < minv) { minv = hi; mini = ib + 1; }
        }
        __syncthreads();   // all readers done before buf is restaged
        buf ^= 1;
    }

    // sortable float key; u64 min reproduces first-index tie-breaking
    unsigned u = __float_as_uint(minv);
    u = (u & 0x80000000u) ? ~u : (u | 0x80000000u);
    ull pk = ((ull)u << 32) | (unsigned)mini;
    atomicMin(&g_packed[token], pk);
}

// ---------------- kernel 3: extract labels as float32 ----------------
__global__ void kfin(float* __restrict__ out) {
    int i = blockIdx.x * blockDim.x + threadIdx.x;
    if (i < TOKENS) out[i] = (float)(unsigned)(g_packed[i] & 0xFFFFFFFFull);
}

// ---------------- launch ----------------
extern "C" void kernel_launch(void* const* d_in, const int* in_sizes, int n_in,
                              void* d_out, int out_size) {
    const float* in = nullptr;
    const float* W  = nullptr;
    const float* cb = nullptr;
    for (int i = 0; i < n_in; ++i) {
        if      (in_sizes[i] == TOKENS * INDIM) in = (const float*)d_in[i];
        else if (in_sizes[i] == CBD * INDIM)    W  = (const float*)d_in[i];
        else if (in_sizes[i] == CBK * CBD)      cb = (const float*)d_in[i];
    }
    if (!in) in = (const float*)d_in[0];
    if (!W)  W  = (const float*)d_in[1];
    if (!cb) cb = (const float*)d_in[2];
    float* out = (float*)d_out;

    kinit<<<TOKENS / 256, 256>>>();
    kprep<<<NPAIR / 128, 128>>>(cb);
    k1<<<TOKENS / 128, 128>>>(in, W);
    k2<<<(TOKENS / 128) * SPLITS, 128>>>();
    kfin<<<TOKENS / 256, 256>>>(out);
}

// round 7
// speedup vs baseline: 1.6869x; 1.1305x over previous
#include <cuda_runtime.h>
#include <cstdint>

typedef unsigned long long ull;

#define TOKENS 32768
#define INDIM  512
#define CBK    8192
#define CBD    16
#define NPAIR  4096          // 8192 codes as 4096 pairs
#define SPLITS 4
#define PAIRS_PER_SPLIT (NPAIR / SPLITS)   // 1024
#define CHUNK  128           // pairs staged per chunk
#define NCHUNKS (PAIRS_PER_SPLIT / CHUNK)  // 8

// ---------------- scratch (device globals; no allocation allowed) ----------------
__device__ __align__(16) float g_targets[TOKENS * CBD];      // 2 MB
__device__ __align__(16) float g_cbpairs[NPAIR * 32];        // interleaved (cA_i, cB_i), 512 KB
__device__ __align__(16) float g_c2[NPAIR * 2];              // (||cA||^2, ||cB||^2), 32 KB
__device__ ull g_packed[TOKENS];                             // sortable-key<<32 | idx

// ---------------- f32x2 helpers (packed fp32, sm_100+) ----------------
__device__ __forceinline__ ull ffma2(ull a, ull b, ull c) {
    ull d; asm("fma.rn.f32x2 %0, %1, %2, %3;" : "=l"(d) : "l"(a), "l"(b), "l"(c)); return d;
}
__device__ __forceinline__ ull mul2(ull a, ull b) {
    ull d; asm("mul.rn.f32x2 %0, %1, %2;" : "=l"(d) : "l"(a), "l"(b)); return d;
}
__device__ __forceinline__ ull add2(ull a, ull b) {
    ull d; asm("add.rn.f32x2 %0, %1, %2;" : "=l"(d) : "l"(a), "l"(b)); return d;
}
__device__ __forceinline__ ull pack2(float lo, float hi) {
    ull d; asm("mov.b64 %0, {%1, %2};" : "=l"(d) : "f"(lo), "f"(hi)); return d;
}
__device__ __forceinline__ void unpack2(ull v, float& lo, float& hi) {
    asm("mov.b64 {%0, %1}, %2;" : "=f"(lo), "=f"(hi) : "l"(v));
}
__device__ __forceinline__ void cp16(uint32_t saddr, const void* g) {
    asm volatile("cp.async.cg.shared.global [%0], [%1], 16;" :: "r"(saddr), "l"(g));
}

// ---------------- kernel 0: interleaved codebook + norms ----------------
__global__ void kprep(const float* __restrict__ cb) {
    int p = blockIdx.x * blockDim.x + threadIdx.x;
    if (p >= NPAIR) return;
    const float* a = cb + (size_t)(2 * p) * CBD;
    const float* b = a + CBD;
    float c2a = 0.f, c2b = 0.f;
#pragma unroll
    for (int i = 0; i < CBD; ++i) {
        float av = a[i], bv = b[i];
        g_cbpairs[p * 32 + 2 * i]     = av;
        g_cbpairs[p * 32 + 2 * i + 1] = bv;
        c2a = fmaf(av, av, c2a);
        c2b = fmaf(bv, bv, c2b);
    }
    g_c2[2 * p]     = c2a;
    g_c2[2 * p + 1] = c2b;
}

// ---------------- kernel 1: projection (also inits g_packed) ----------------
__global__ void __launch_bounds__(128) k1(const float* __restrict__ in, const float* __restrict__ W) {
    __shared__ __align__(16) float sWt[INDIM * CBD];   // transposed W: [d][j], 32 KB
    int tid = threadIdx.x;
    for (int idx = tid; idx < CBD * INDIM; idx += 128) {
        int j = idx >> 9;          // 0..15
        int d = idx & 511;
        sWt[d * CBD + j] = W[idx];
    }
    __syncthreads();

    int r = blockIdx.x * 128 + tid;
    g_packed[r] = ~0ull;           // fold init here (one thread per token)

    const float4* xin = reinterpret_cast<const float4*>(in + (size_t)r * INDIM);
    ull acc[8];
#pragma unroll
    for (int k = 0; k < 8; ++k) acc[k] = 0ull;

#pragma unroll 2
    for (int d4 = 0; d4 < INDIM / 4; ++d4) {
        float4 xv = xin[d4];
        float xs[4] = {xv.x, xv.y, xv.z, xv.w};
#pragma unroll
        for (int dd = 0; dd < 4; ++dd) {
            ull xd = pack2(xs[dd], xs[dd]);
            const ulonglong2* wd = reinterpret_cast<const ulonglong2*>(sWt + (d4 * 4 + dd) * CBD);
            ulonglong2 w0 = wd[0], w1 = wd[1], w2 = wd[2], w3 = wd[3];
            acc[0] = ffma2(w0.x, xd, acc[0]); acc[1] = ffma2(w0.y, xd, acc[1]);
            acc[2] = ffma2(w1.x, xd, acc[2]); acc[3] = ffma2(w1.y, xd, acc[3]);
            acc[4] = ffma2(w2.x, xd, acc[4]); acc[5] = ffma2(w2.y, xd, acc[5]);
            acc[6] = ffma2(w3.x, xd, acc[6]); acc[7] = ffma2(w3.y, xd, acc[7]);
        }
    }

    float4* out4 = reinterpret_cast<float4*>(g_targets + (size_t)r * CBD);
    float4 o;
    unpack2(acc[0], o.x, o.y); unpack2(acc[1], o.z, o.w); out4[0] = o;
    unpack2(acc[2], o.x, o.y); unpack2(acc[3], o.z, o.w); out4[1] = o;
    unpack2(acc[4], o.x, o.y); unpack2(acc[5], o.z, o.w); out4[2] = o;
    unpack2(acc[6], o.x, o.y); unpack2(acc[7], o.z, o.w); out4[3] = o;
}

// ---------------- kernel 2: argmin scan, 2 tokens/thread, 4-way split ----------------
// score(c) = ||c||^2 - 2 t.c  computed as  c2 + sum_i (-2 t_i) c_i
__global__ void __launch_bounds__(128, 4) k2() {
    __shared__ __align__(16) float sD[2][CHUNK * 32];   // 16 KB per buffer
    __shared__ __align__(16) float sC2[2][CHUNK * 2];   // 1 KB per buffer

    int tid    = threadIdx.x;
    int split  = blockIdx.x & (SPLITS - 1);
    int tokBase = (blockIdx.x >> 2) * 256;
    int tokenA = tokBase + tid;
    int tokenB = tokBase + 128 + tid;
    int baseP  = split * PAIRS_PER_SPLIT;

    // load targets, scale by -2, duplicate into f32x2
    ull tdA[16], tdB[16];
    {
        const float4* t4 = reinterpret_cast<const float4*>(g_targets + (size_t)tokenA * CBD);
        float4 a = t4[0], b = t4[1], c = t4[2], d = t4[3];
        float v[16] = {a.x,a.y,a.z,a.w, b.x,b.y,b.z,b.w, c.x,c.y,c.z,c.w, d.x,d.y,d.z,d.w};
#pragma unroll
        for (int i = 0; i < 16; ++i) { float s = -2.f * v[i]; tdA[i] = pack2(s, s); }
    }
    {
        const float4* t4 = reinterpret_cast<const float4*>(g_targets + (size_t)tokenB * CBD);
        float4 a = t4[0], b = t4[1], c = t4[2], d = t4[3];
        float v[16] = {a.x,a.y,a.z,a.w, b.x,b.y,b.z,b.w, c.x,c.y,c.z,c.w, d.x,d.y,d.z,d.w};
#pragma unroll
        for (int i = 0; i < 16; ++i) { float s = -2.f * v[i]; tdB[i] = pack2(s, s); }
    }

    float bestA = __int_as_float(0x7F800000), bestB = bestA;   // +inf
    int   idxA = 0, idxB = 0;

    auto stage = [&](int chunk, int buf) {
        const float4* src = reinterpret_cast<const float4*>(g_cbpairs + (size_t)(baseP + chunk * CHUNK) * 32);
        uint32_t sd = (uint32_t)__cvta_generic_to_shared(&sD[buf][0]);
        for (int k = tid; k < CHUNK * 8; k += 128)            // 1024 x 16B
            cp16(sd + k * 16, src + k);
        const float4* s2 = reinterpret_cast<const float4*>(g_c2 + (size_t)(baseP + chunk * CHUNK) * 2);
        uint32_t sc = (uint32_t)__cvta_generic_to_shared(&sC2[buf][0]);
        if (tid < CHUNK * 2 / 4)                               // 64 x 16B
            cp16(sc + tid * 16, s2 + tid);
        asm volatile("cp.async.commit_group;" ::: "memory");
    };

    int buf = 0;
    stage(0, 0);
    for (int chunk = 0; chunk < NCHUNKS; ++chunk) {
        if (chunk + 1 < NCHUNKS) {
            stage(chunk + 1, buf ^ 1);
            asm volatile("cp.async.wait_group 1;" ::: "memory");
        } else {
            asm volatile("cp.async.wait_group 0;" ::: "memory");
        }
        __syncthreads();

        const float* sdp = sD[buf];
        const ull*   c2p = reinterpret_cast<const ull*>(&sC2[buf][0]);
        int gp0 = baseP + chunk * CHUNK;

#pragma unroll 2
        for (int p = 0; p < CHUNK; ++p) {
            const ulonglong2* cp = reinterpret_cast<const ulonglong2*>(sdp + p * 32);
            ulonglong2 q0 = cp[0], q1 = cp[1], q2 = cp[2], q3 = cp[3];
            ulonglong2 q4 = cp[4], q5 = cp[5], q6 = cp[6], q7 = cp[7];
            ull c2v = c2p[p];

            ull a0 = ffma2(tdA[0], q0.x, c2v);    ull a1 = mul2(tdA[1], q0.y);
            ull b0 = ffma2(tdB[0], q0.x, c2v);    ull b1 = mul2(tdB[1], q0.y);
            a0 = ffma2(tdA[2],  q1.x, a0);        a1 = ffma2(tdA[3],  q1.y, a1);
            b0 = ffma2(tdB[2],  q1.x, b0);        b1 = ffma2(tdB[3],  q1.y, b1);
            a0 = ffma2(tdA[4],  q2.x, a0);        a1 = ffma2(tdA[5],  q2.y, a1);
            b0 = ffma2(tdB[4],  q2.x, b0);        b1 = ffma2(tdB[5],  q2.y, b1);
            a0 = ffma2(tdA[6],  q3.x, a0);        a1 = ffma2(tdA[7],  q3.y, a1);
            b0 = ffma2(tdB[6],  q3.x, b0);        b1 = ffma2(tdB[7],  q3.y, b1);
            a0 = ffma2(tdA[8],  q4.x, a0);        a1 = ffma2(tdA[9],  q4.y, a1);
            b0 = ffma2(tdB[8],  q4.x, b0);        b1 = ffma2(tdB[9],  q4.y, b1);
            a0 = ffma2(tdA[10], q5.x, a0);        a1 = ffma2(tdA[11], q5.y, a1);
            b0 = ffma2(tdB[10], q5.x, b0);        b1 = ffma2(tdB[11], q5.y, b1);
            a0 = ffma2(tdA[12], q6.x, a0);        a1 = ffma2(tdA[13], q6.y, a1);
            b0 = ffma2(tdB[12], q6.x, b0);        b1 = ffma2(tdB[13], q6.y, b1);
            a0 = ffma2(tdA[14], q7.x, a0);        a1 = ffma2(tdA[15], q7.y, a1);
            b0 = ffma2(tdB[14], q7.x, b0);        b1 = ffma2(tdB[15], q7.y, b1);

            ull sA = add2(a0, a1);
            ull sB = add2(b0, b1);
            float loA, hiA, loB, hiB;
            unpack2(sA, loA, hiA);
            unpack2(sB, loB, hiB);
            int ib = 2 * (gp0 + p);
            if (loA < bestA) { bestA = loA; idxA = ib; }
            if (hiA < bestA) { bestA = hiA; idxA = ib + 1; }
            if (loB < bestB) { bestB = loB; idxB = ib; }
            if (hiB < bestB) { bestB = hiB; idxB = ib + 1; }
        }
        __syncthreads();   // all readers done before buf is restaged
        buf ^= 1;
    }

    // sortable float key; u64 min reproduces first-index tie-breaking
    unsigned uA = __float_as_uint(bestA);
    uA = (uA & 0x80000000u) ? ~uA : (uA | 0x80000000u);
    atomicMin(&g_packed[tokenA], ((ull)uA << 32) | (unsigned)idxA);
    unsigned uB = __float_as_uint(bestB);
    uB = (uB & 0x80000000u) ? ~uB : (uB | 0x80000000u);
    atomicMin(&g_packed[tokenB], ((ull)uB << 32) | (unsigned)idxB);
}

// ---------------- kernel 3: extract labels as float32 ----------------
__global__ void kfin(float* __restrict__ out) {
    int i = blockIdx.x * blockDim.x + threadIdx.x;
    if (i < TOKENS) out[i] = (float)(unsigned)(g_packed[i] & 0xFFFFFFFFull);
}

// ---------------- launch ----------------
extern "C" void kernel_launch(void* const* d_in, const int* in_sizes, int n_in,
                              void* d_out, int out_size) {
    const float* in = nullptr;
    const float* W  = nullptr;
    const float* cb = nullptr;
    for (int i = 0; i < n_in; ++i) {
        if      (in_sizes[i] == TOKENS * INDIM) in = (const float*)d_in[i];
        else if (in_sizes[i] == CBD * INDIM)    W  = (const float*)d_in[i];
        else if (in_sizes[i] == CBK * CBD)      cb = (const float*)d_in[i];
    }
    if (!in) in = (const float*)d_in[0];
    if (!W)  W  = (const float*)d_in[1];
    if (!cb) cb = (const float*)d_in[2];
    float* out = (float*)d_out;

    kprep<<<NPAIR / 128, 128>>>(cb);
    k1<<<TOKENS / 128, 128>>>(in, W);
    k2<<<(TOKENS / 256) * SPLITS, 128>>>();
    kfin<<<TOKENS / 256, 256>>>(out);
}

// round 8
// speedup vs baseline: 1.7528x; 1.0391x over previous
#include <cuda_runtime.h>
#include <cstdint>

typedef unsigned long long ull;

#define TOKENS 32768
#define INDIM  512
#define CBK    8192
#define CBD    16
#define SPLITS 16
#define CODES_PER_SPLIT (CBK / SPLITS)     // 512
#define CHUNK  128                          // codes staged per chunk
#define NCHUNKS (CODES_PER_SPLIT / CHUNK)   // 4
#define TPT    4                            // tokens per thread
#define TOK_PER_BLOCK (128 * TPT)           // 512
#define TGROUPS (TOKENS / TOK_PER_BLOCK)    // 64

// ---------------- scratch (device globals; no allocation allowed) ----------------
__device__ __align__(16) float g_targets[TOKENS * CBD];   // 2 MB
__device__ __align__(16) float g_cbdup[CBK * 32];         // each dim duplicated: (c_i,c_i), 1 MB
__device__ __align__(16) float g_c2dup[CBK * 2];          // (||c||^2, ||c||^2), 64 KB
__device__ ull g_packed[TOKENS];                          // sortable-key<<32 | idx

// ---------------- f32x2 helpers ----------------
__device__ __forceinline__ ull ffma2(ull a, ull b, ull c) {
    ull d; asm("fma.rn.f32x2 %0, %1, %2, %3;" : "=l"(d) : "l"(a), "l"(b), "l"(c)); return d;
}
__device__ __forceinline__ ull add2(ull a, ull b) {
    ull d; asm("add.rn.f32x2 %0, %1, %2;" : "=l"(d) : "l"(a), "l"(b)); return d;
}
__device__ __forceinline__ ull pack2(float lo, float hi) {
    ull d; asm("mov.b64 %0, {%1, %2};" : "=l"(d) : "f"(lo), "f"(hi)); return d;
}
__device__ __forceinline__ void unpack2(ull v, float& lo, float& hi) {
    asm("mov.b64 {%0, %1}, %2;" : "=f"(lo), "=f"(hi) : "l"(v));
}
__device__ __forceinline__ void cp16(uint32_t saddr, const void* g) {
    asm volatile("cp.async.cg.shared.global [%0], [%1], 16;" :: "r"(saddr), "l"(g));
}

// ---------------- kernel 0: dim-duplicated codebook + norms ----------------
__global__ void kprep(const float* __restrict__ cb) {
    int c = blockIdx.x * blockDim.x + threadIdx.x;
    if (c >= CBK) return;
    const float* row = cb + (size_t)c * CBD;
    float s2 = 0.f;
#pragma unroll
    for (int i = 0; i < CBD; ++i) {
        float v = row[i];
        g_cbdup[c * 32 + 2 * i]     = v;
        g_cbdup[c * 32 + 2 * i + 1] = v;
        s2 = fmaf(v, v, s2);
    }
    g_c2dup[2 * c]     = s2;
    g_c2dup[2 * c + 1] = s2;
}

// ---------------- kernel 1: projection, 2 threads per row (also inits g_packed) ----------------
__global__ void __launch_bounds__(128) k1(const float* __restrict__ in, const float* __restrict__ W) {
    __shared__ __align__(16) float sWt[INDIM * CBD];   // transposed W: [d][j], 32 KB
    int tid = threadIdx.x;
    for (int idx = tid; idx < CBD * INDIM; idx += 128) {
        int j = idx >> 9;
        int d = idx & 511;
        sWt[d * CBD + j] = W[idx];
    }
    __syncthreads();

    int gt   = blockIdx.x * 128 + tid;
    int r    = gt >> 1;            // row
    int half = gt & 1;             // which 256-dim half
    if (half == 0) g_packed[r] = ~0ull;

    const float4* xin = reinterpret_cast<const float4*>(in + (size_t)r * INDIM) + half * 64;
    ull acc[8];
#pragma unroll
    for (int k = 0; k < 8; ++k) acc[k] = 0ull;

#pragma unroll 2
    for (int d4 = 0; d4 < 64; ++d4) {
        float4 xv = xin[d4];
        float xs[4] = {xv.x, xv.y, xv.z, xv.w};
        int dbase = half * 256 + d4 * 4;
#pragma unroll
        for (int dd = 0; dd < 4; ++dd) {
            ull xd = pack2(xs[dd], xs[dd]);
            const ulonglong2* wd = reinterpret_cast<const ulonglong2*>(sWt + (dbase + dd) * CBD);
            ulonglong2 w0 = wd[0], w1 = wd[1], w2 = wd[2], w3 = wd[3];
            acc[0] = ffma2(w0.x, xd, acc[0]); acc[1] = ffma2(w0.y, xd, acc[1]);
            acc[2] = ffma2(w1.x, xd, acc[2]); acc[3] = ffma2(w1.y, xd, acc[3]);
            acc[4] = ffma2(w2.x, xd, acc[4]); acc[5] = ffma2(w2.y, xd, acc[5]);
            acc[6] = ffma2(w3.x, xd, acc[6]); acc[7] = ffma2(w3.y, xd, acc[7]);
        }
    }

    // combine the two halves via lane-pair shuffle
#pragma unroll
    for (int k = 0; k < 8; ++k) {
        ull other = __shfl_xor_sync(0xFFFFFFFFu, acc[k], 1);
        acc[k] = add2(acc[k], other);
    }

    if (half == 0) {
        float4* out4 = reinterpret_cast<float4*>(g_targets + (size_t)r * CBD);
        float4 o;
        unpack2(acc[0], o.x, o.y); unpack2(acc[1], o.z, o.w); out4[0] = o;
        unpack2(acc[2], o.x, o.y); unpack2(acc[3], o.z, o.w); out4[1] = o;
        unpack2(acc[4], o.x, o.y); unpack2(acc[5], o.z, o.w); out4[2] = o;
        unpack2(acc[6], o.x, o.y); unpack2(acc[7], o.z, o.w); out4[3] = o;
    }
}

// ---------------- kernel 2: argmin scan, tokens-in-lanes, 4 tokens/thread ----------------
// score(c) = ||c||^2 + sum_i (-2 t_i) c_i ; lanes = (tokenX, tokenY), code dims duplicated
__global__ void __launch_bounds__(128, 4) k2() {
    __shared__ __align__(16) float sD[2][CHUNK * 32];   // 16 KB per buffer (dup'd codes)
    __shared__ __align__(16) float sC2[2][CHUNK * 2];   // 1 KB per buffer (dup'd norms)

    int tid   = threadIdx.x;
    int split = blockIdx.x & (SPLITS - 1);
    int group = blockIdx.x >> 4;                 // log2(SPLITS)=4
    int tokBase = group * TOK_PER_BLOCK;
    int tokA = tokBase + tid;
    int tokB = tokBase + 128 + tid;
    int tokC = tokBase + 256 + tid;
    int tokD = tokBase + 384 + tid;
    int baseC = split * CODES_PER_SPLIT;

    // targets packed two-per-lane-pair, pre-scaled by -2
    ull tAB[16], tCD[16];
    {
        const float4* pA = reinterpret_cast<const float4*>(g_targets + (size_t)tokA * CBD);
        const float4* pB = reinterpret_cast<const float4*>(g_targets + (size_t)tokB * CBD);
        float4 a0 = pA[0], a1 = pA[1], a2 = pA[2], a3 = pA[3];
        float4 b0 = pB[0], b1 = pB[1], b2 = pB[2], b3 = pB[3];
        float va[16] = {a0.x,a0.y,a0.z,a0.w, a1.x,a1.y,a1.z,a1.w, a2.x,a2.y,a2.z,a2.w, a3.x,a3.y,a3.z,a3.w};
        float vb[16] = {b0.x,b0.y,b0.z,b0.w, b1.x,b1.y,b1.z,b1.w, b2.x,b2.y,b2.z,b2.w, b3.x,b3.y,b3.z,b3.w};
#pragma unroll
        for (int i = 0; i < 16; ++i) tAB[i] = pack2(-2.f * va[i], -2.f * vb[i]);
    }
    {
        const float4* pC = reinterpret_cast<const float4*>(g_targets + (size_t)tokC * CBD);
        const float4* pD = reinterpret_cast<const float4*>(g_targets + (size_t)tokD * CBD);
        float4 a0 = pC[0], a1 = pC[1], a2 = pC[2], a3 = pC[3];
        float4 b0 = pD[0], b1 = pD[1], b2 = pD[2], b3 = pD[3];
        float va[16] = {a0.x,a0.y,a0.z,a0.w, a1.x,a1.y,a1.z,a1.w, a2.x,a2.y,a2.z,a2.w, a3.x,a3.y,a3.z,a3.w};
        float vb[16] = {b0.x,b0.y,b0.z,b0.w, b1.x,b1.y,b1.z,b1.w, b2.x,b2.y,b2.z,b2.w, b3.x,b3.y,b3.z,b3.w};
#pragma unroll
        for (int i = 0; i < 16; ++i) tCD[i] = pack2(-2.f * va[i], -2.f * vb[i]);
    }

    float bA = __int_as_float(0x7F800000), bB = bA, bC = bA, bD = bA;
    int   iA = 0, iB = 0, iC = 0, iD = 0;

    auto stage = [&](int chunk, int buf) {
        const float4* src = reinterpret_cast<const float4*>(g_cbdup + (size_t)(baseC + chunk * CHUNK) * 32);
        uint32_t sd = (uint32_t)__cvta_generic_to_shared(&sD[buf][0]);
        for (int k = tid; k < CHUNK * 8; k += 128)            // 1024 x 16B
            cp16(sd + k * 16, src + k);
        const float4* s2 = reinterpret_cast<const float4*>(g_c2dup + (size_t)(baseC + chunk * CHUNK) * 2);
        uint32_t sc = (uint32_t)__cvta_generic_to_shared(&sC2[buf][0]);
        if (tid < CHUNK * 2 / 4)                               // 64 x 16B
            cp16(sc + tid * 16, s2 + tid);
        asm volatile("cp.async.commit_group;" ::: "memory");
    };

    int buf = 0;
    stage(0, 0);
    for (int chunk = 0; chunk < NCHUNKS; ++chunk) {
        if (chunk + 1 < NCHUNKS) {
            stage(chunk + 1, buf ^ 1);
            asm volatile("cp.async.wait_group 1;" ::: "memory");
        } else {
            asm volatile("cp.async.wait_group 0;" ::: "memory");
        }
        __syncthreads();

        const float* sdp = sD[buf];
        const ull*   c2p = reinterpret_cast<const ull*>(&sC2[buf][0]);
        int gc0 = baseC + chunk * CHUNK;

#pragma unroll 2
        for (int p = 0; p < CHUNK; ++p) {
            const ulonglong2* cp = reinterpret_cast<const ulonglong2*>(sdp + p * 32);
            ulonglong2 q0 = cp[0], q1 = cp[1], q2 = cp[2], q3 = cp[3];
            ulonglong2 q4 = cp[4], q5 = cp[5], q6 = cp[6], q7 = cp[7];
            ull c2v = c2p[p];

            // 16-deep chains, one per token pair; c2 as chain seed
            ull sAB = ffma2(tAB[0],  q0.x, c2v);   ull sCD = ffma2(tCD[0],  q0.x, c2v);
            sAB = ffma2(tAB[1],  q0.y, sAB);       sCD = ffma2(tCD[1],  q0.y, sCD);
            sAB = ffma2(tAB[2],  q1.x, sAB);       sCD = ffma2(tCD[2],  q1.x, sCD);
            sAB = ffma2(tAB[3],  q1.y, sAB);       sCD = ffma2(tCD[3],  q1.y, sCD);
            sAB = ffma2(tAB[4],  q2.x, sAB);       sCD = ffma2(tCD[4],  q2.x, sCD);
            sAB = ffma2(tAB[5],  q2.y, sAB);       sCD = ffma2(tCD[5],  q2.y, sCD);
            sAB = ffma2(tAB[6],  q3.x, sAB);       sCD = ffma2(tCD[6],  q3.x, sCD);
            sAB = ffma2(tAB[7],  q3.y, sAB);       sCD = ffma2(tCD[7],  q3.y, sCD);
            sAB = ffma2(tAB[8],  q4.x, sAB);       sCD = ffma2(tCD[8],  q4.x, sCD);
            sAB = ffma2(tAB[9],  q4.y, sAB);       sCD = ffma2(tCD[9],  q4.y, sCD);
            sAB = ffma2(tAB[10], q5.x, sAB);       sCD = ffma2(tCD[10], q5.x, sCD);
            sAB = ffma2(tAB[11], q5.y, sAB);       sCD = ffma2(tCD[11], q5.y, sCD);
            sAB = ffma2(tAB[12], q6.x, sAB);       sCD = ffma2(tCD[12], q6.x, sCD);
            sAB = ffma2(tAB[13], q6.y, sAB);       sCD = ffma2(tCD[13], q6.y, sCD);
            sAB = ffma2(tAB[14], q7.x, sAB);       sCD = ffma2(tCD[14], q7.x, sCD);
            sAB = ffma2(tAB[15], q7.y, sAB);       sCD = ffma2(tCD[15], q7.y, sCD);

            float scA, scB, scC, scD;
            unpack2(sAB, scA, scB);
            unpack2(sCD, scC, scD);
            int ic = gc0 + p;
            if (scA < bA) { bA = scA; iA = ic; }
            if (scB < bB) { bB = scB; iB = ic; }
            if (scC < bC) { bC = scC; iC = ic; }
            if (scD < bD) { bD = scD; iD = ic; }
        }
        __syncthreads();   // readers done before restage
        buf ^= 1;
    }

    // sortable float key; u64 min reproduces first-index tie-breaking
    unsigned u;
    u = __float_as_uint(bA); u = (u & 0x80000000u) ? ~u : (u | 0x80000000u);
    atomicMin(&g_packed[tokA], ((ull)u << 32) | (unsigned)iA);
    u = __float_as_uint(bB); u = (u & 0x80000000u) ? ~u : (u | 0x80000000u);
    atomicMin(&g_packed[tokB], ((ull)u << 32) | (unsigned)iB);
    u = __float_as_uint(bC); u = (u & 0x80000000u) ? ~u : (u | 0x80000000u);
    atomicMin(&g_packed[tokC], ((ull)u << 32) | (unsigned)iC);
    u = __float_as_uint(bD); u = (u & 0x80000000u) ? ~u : (u | 0x80000000u);
    atomicMin(&g_packed[tokD], ((ull)u << 32) | (unsigned)iD);
}

// ---------------- kernel 3: extract labels as float32 ----------------
__global__ void kfin(float* __restrict__ out) {
    int i = blockIdx.x * blockDim.x + threadIdx.x;
    if (i < TOKENS) out[i] = (float)(unsigned)(g_packed[i] & 0xFFFFFFFFull);
}

// ---------------- launch ----------------
extern "C" void kernel_launch(void* const* d_in, const int* in_sizes, int n_in,
                              void* d_out, int out_size) {
    const float* in = nullptr;
    const float* W  = nullptr;
    const float* cb = nullptr;
    for (int i = 0; i < n_in; ++i) {
        if      (in_sizes[i] == TOKENS * INDIM) in = (const float*)d_in[i];
        else if (in_sizes[i] == CBD * INDIM)    W  = (const float*)d_in[i];
        else if (in_sizes[i] == CBK * CBD)      cb = (const float*)d_in[i];
    }
    if (!in) in = (const float*)d_in[0];
    if (!W)  W  = (const float*)d_in[1];
    if (!cb) cb = (const float*)d_in[2];
    float* out = (float*)d_out;

    kprep<<<CBK / 128, 128>>>(cb);
    k1<<<(TOKENS * 2) / 128, 128>>>(in, W);
    k2<<<TGROUPS * SPLITS, 128>>>();
    kfin<<<TOKENS / 256, 256>>>(out);
}